// round 5
// baseline (speedup 1.0000x reference)
#include <cuda_runtime.h>
#include <math.h>

#define BB   1024
#define TT   512
#define HH   64
#define KK   128
#define ROWS 8
#define NTHR 512
#define IPITCH 132         // words per input row in ib
#define RPITCH 260         // pitch for red/act arrays
#define LOG2E 1.4426950408889634f

// Scratch (static __device__ arrays are the allowed scratch mechanism)
__device__ float g_h1[(size_t)BB * TT * HH];   // layer-0 hidden sequence [B][T][H]
__device__ float g_hlast[BB * HH];             // layer-1 final hidden state

__device__ __forceinline__ void fma2(unsigned long long &d,
                                     unsigned long long a, unsigned long long b) {
    asm("fma.rn.f32x2 %0, %1, %2, %0;" : "+l"(d) : "l"(a), "l"(b));
}
__device__ __forceinline__ unsigned long long pack2(float lo, float hi) {
    unsigned long long r;
    asm("mov.b64 %0, {%1, %2};" : "=l"(r) : "f"(lo), "f"(hi));
    return r;
}
__device__ __forceinline__ float2 unpack2(unsigned long long v) {
    float2 f; asm("mov.b64 {%0, %1}, %2;" : "=f"(f.x), "=f"(f.y) : "l"(v)); return f;
}
__device__ __forceinline__ float ex2f(float x) {
    float r; asm("ex2.approx.f32 %0, %1;" : "=f"(r) : "f"(x)); return r;
}
__device__ __forceinline__ float rcpf(float x) {
    float r; asm("rcp.approx.f32 %0, %1;" : "=f"(r) : "f"(x)); return r;
}
__device__ __forceinline__ float ftanhf(float x) {    // tanh = 2*sig(2x)-1
    return fmaf(rcpf(1.0f + ex2f(-2.0f * LOG2E * x)), 2.0f, -1.0f);
}

// Persistent-weight LSTM layer. 512 threads = (col c 0..255) x (khalf 0/1).
// col c is the gate-major weight row (gate q = c>>6, unit j = c&63).
// Thread holds W[c][khalf*64 .. +63] in 32 fp32x2 REGISTERS -> zero weight
// smem traffic. v = [h;x] is broadcast from smem (warp-uniform LDS.128).
// Accumulators are fp32x2 packed over (row-pair is NOT packed; k-parity is):
// acc[r] accumulates {even-k, odd-k} halves for batch row r.
// Cross-khalf reduction and gate regrouping go through small smem arrays.
__global__ void __launch_bounds__(NTHR, 1)
lstm_layer(const float* __restrict__ x_in,
           const float* __restrict__ w_ih, const float* __restrict__ w_hh,
           const float* __restrict__ b_ih, const float* __restrict__ b_hh,
           int store_seq, int store_last, int x_is_scratch)
{
    __shared__ float ib[ROWS * IPITCH];          // v buffer: h in [0,64), x in [64,128)
    __shared__ float red[2 * ROWS * RPITCH];     // partial sums [khalf][row][c]
    __shared__ float act[ROWS * RPITCH];         // gate activations [row][c]

    const float* xp = x_is_scratch ? g_h1 : x_in;

    const int tid = threadIdx.x;
    const int c   = tid & 255;          // gate-major column
    const int kh  = tid >> 8;           // k half: 0 -> h-part (w_hh), 1 -> x-part (w_ih)
    const int row_base = blockIdx.x * ROWS;

    // ---- weights into registers: W[c][kh*64 + 2m], W[c][kh*64 + 2m+1]
    unsigned long long wreg[32];
    {
        const float* wsrc = (kh == 0) ? (w_hh + c * 64) : (w_ih + c * 64);
        #pragma unroll
        for (int m = 0; m < 32; m++) {
            float2 w2 = reinterpret_cast<const float2*>(wsrc)[m];
            wreg[m] = pack2(w2.x, w2.y);
        }
    }
    const float bias = b_ih[c] + b_hh[c];
    // branchless activation params for column c (gate q=c>>6; tanh iff q==2)
    const int   qg     = c >> 6;
    const float mscale = (qg == 2) ? (-2.0f * LOG2E) : (-LOG2E);
    const float po     = (qg == 2) ? 2.0f : 1.0f;
    const float pc     = (qg == 2) ? -1.0f : 0.0f;

    // ---- init v buffer: h = 0, x = x[:, 0, :]  (512 threads cover 8x64 each part)
    {
        int r = tid & 7, u = (tid >> 3) & 63;
        ib[r * IPITCH + u]      = 0.0f;
        ib[r * IPITCH + 64 + u] = xp[(size_t)(row_base + r) * TT * HH + u];
    }

    // ---- update-thread mapping: threads with c<128 own slot = (c&127) + 128*kh
    const int  slot   = (c & 127) + 128 * kh;   // 0..255
    const int  ju     = slot & 63;              // unit
    const int  pu     = slot >> 6;              // row pair 0..3 -> rows 2pu, 2pu+1
    const bool is_upd = (c < 128);
    float cst0 = 0.0f, cst1 = 0.0f;             // cell states for rows 2pu, 2pu+1

    // ---- x-prefetch mapping: threads with c>=128 (256 threads, 2 slots each)
    const bool is_xf = (c >= 128);
    const int  t2  = (c - 128) + 128 * kh;      // 0..255
    const int  xr  = t2 >> 6;                   // rows xr and xr+4
    const int  xd  = t2 & 63;
    const float* xrow = xp + (size_t)(row_base + xr) * TT * HH + xd;

    __syncthreads();

    for (int t = 0; t < TT; t++) {
        // prefetch x for step t+1 (LDG latency hidden under the k-loop)
        int tn = (t + 1 < TT) ? (t + 1) : t;
        float xa = 0.0f, xb = 0.0f;
        if (is_xf) {
            xa = xrow[(size_t)tn * HH];
            xb = xrow[(size_t)tn * HH + (size_t)4 * TT * HH];
        }

        // ---- k-loop: acc[r] += v_r[k] * W[c][k] over this thread's 64 ks
        unsigned long long acc[8];
        #pragma unroll
        for (int r = 0; r < 8; r++) acc[r] = 0ull;

        const float* vb = ib + kh * 64;
        #pragma unroll
        for (int n = 0; n < 16; n++) {
            #pragma unroll
            for (int r = 0; r < 8; r++) {
                ulonglong2 vv = *reinterpret_cast<const ulonglong2*>(vb + r * IPITCH + n * 4);
                fma2(acc[r], vv.x, wreg[2 * n]);
                fma2(acc[r], vv.y, wreg[2 * n + 1]);
            }
        }

        // ---- publish partials (all 8 rows)
        float part[8];
        #pragma unroll
        for (int r = 0; r < 8; r++) {
            float2 fr = unpack2(acc[r]);
            part[r] = fr.x + fr.y;
            red[(kh * ROWS + r) * RPITCH + c] = part[r];
        }
        __syncthreads();

        // ---- combine + activate my 4 rows (kh0: rows 0-3, kh1: rows 4-7)
        {
            const int rbase = kh * 4;
            #pragma unroll
            for (int rr = 0; rr < 4; rr++) {
                int r = rbase + rr;
                float other = red[((1 - kh) * ROWS + r) * RPITCH + c];
                float z = part[r] + other + bias;
                float a = fmaf(rcpf(1.0f + ex2f(z * mscale)), po, pc);
                act[r * RPITCH + c] = a;
            }
        }
        __syncthreads();

        // ---- state update (256 update threads) + stage next-step inputs
        float h0 = 0.0f, h1 = 0.0f;
        if (is_upd) {
            int r0 = pu * 2;
            float i0 = act[r0 * RPITCH + ju];
            float f0 = act[r0 * RPITCH + 64 + ju];
            float g0 = act[r0 * RPITCH + 128 + ju];
            float o0 = act[r0 * RPITCH + 192 + ju];
            float i1 = act[(r0 + 1) * RPITCH + ju];
            float f1 = act[(r0 + 1) * RPITCH + 64 + ju];
            float g1 = act[(r0 + 1) * RPITCH + 128 + ju];
            float o1 = act[(r0 + 1) * RPITCH + 192 + ju];

            cst0 = f0 * cst0 + i0 * g0;
            cst1 = f1 * cst1 + i1 * g1;
            h0 = o0 * ftanhf(cst0);
            h1 = o1 * ftanhf(cst1);

            ib[r0 * IPITCH + ju]       = h0;
            ib[(r0 + 1) * IPITCH + ju] = h1;
        }
        if (is_xf) {
            ib[xr * IPITCH + 64 + xd]       = xa;
            ib[(xr + 4) * IPITCH + 64 + xd] = xb;
        }

        if (store_seq && is_upd) {
            int r0 = pu * 2;
            g_h1[((size_t)(row_base + r0) * TT + t) * HH + ju]     = h0;
            g_h1[((size_t)(row_base + r0 + 1) * TT + t) * HH + ju] = h1;
        }
        if (store_last && is_upd && t == TT - 1) {
            int r0 = pu * 2;
            g_hlast[(row_base + r0) * HH + ju]     = h0;
            g_hlast[(row_base + r0 + 1) * HH + ju] = h1;
        }

        __syncthreads();
    }
}

// out[b][o] = softplus(h_last[b] . fc_w[o] + fc_b[o]),  O=32
__global__ void fc_softplus(const float* __restrict__ fc_w,
                            const float* __restrict__ fc_b,
                            float* __restrict__ out)
{
    __shared__ float wsh[64 * 32];   // [k][o] transposed
    __shared__ float bsh[32];
    const int tid = threadIdx.x;     // 128 threads

    for (int idx = tid; idx < 64 * 32; idx += 128) {
        int k = idx >> 5, o = idx & 31;
        wsh[idx] = fc_w[o * 64 + k];
    }
    if (tid < 32) bsh[tid] = fc_b[tid];
    __syncthreads();

    int gid = blockIdx.x * 128 + tid;
    int b = gid >> 5, o = gid & 31;
    const float* hr = g_hlast + b * 64;

    float z = bsh[o];
    #pragma unroll
    for (int k = 0; k < 64; k++)
        z += hr[k] * wsh[k * 32 + o];

    float r = (z > 20.0f) ? z : log1pf(__expf(z));
    out[gid] = r;
}

extern "C" void kernel_launch(void* const* d_in, const int* in_sizes, int n_in,
                              void* d_out, int out_size)
{
    (void)in_sizes; (void)n_in; (void)out_size;
    const float* x    = (const float*)d_in[0];
    const float* wih0 = (const float*)d_in[1];
    const float* whh0 = (const float*)d_in[2];
    const float* bih0 = (const float*)d_in[3];
    const float* bhh0 = (const float*)d_in[4];
    const float* wih1 = (const float*)d_in[5];
    const float* whh1 = (const float*)d_in[6];
    const float* bih1 = (const float*)d_in[7];
    const float* bhh1 = (const float*)d_in[8];
    const float* fcw  = (const float*)d_in[9];
    const float* fcb  = (const float*)d_in[10];
    float* out = (float*)d_out;

    // layer 0: reads x, stores full h1 sequence
    lstm_layer<<<BB / ROWS, NTHR>>>(x, wih0, whh0, bih0, bhh0, 1, 0, 0);
    // layer 1: reads h1 scratch, stores only final h
    lstm_layer<<<BB / ROWS, NTHR>>>(nullptr, wih1, whh1, bih1, bhh1, 0, 1, 1);
    // FC + softplus
    fc_softplus<<<(BB * 32) / 128, 128>>>(fcw, fcb, out);
}

// round 6
// speedup vs baseline: 1.1223x; 1.1223x over previous
#include <cuda_runtime.h>
#include <math.h>

#define BB   1024
#define TT   512
#define HH   64
#define ROWS 8
#define NTHR 256
#define IPITCH 68          // words per row in smem tiles (conflict-free padding)
#define TCH  8             // t-chunks for pre-GEMM
#define TPC  (TT / TCH)    // 64 timesteps per pre-GEMM CTA
#define LOG2E 1.4426950408889634f

// Scratch (static __device__ arrays are the allowed scratch mechanism)
__device__ float g_h1[(size_t)BB * TT * HH];     // layer-0 hidden sequence [B][T][H]
__device__ float g_pre[(size_t)BB * TT * 256];   // x-projection [cta][t][g][r] (512 MB)
__device__ float g_hlast[BB * HH];               // layer-1 final hidden state

__device__ __forceinline__ void fma2(unsigned long long &d,
                                     unsigned long long a, unsigned long long b) {
    asm("fma.rn.f32x2 %0, %1, %2, %0;" : "+l"(d) : "l"(a), "l"(b));
}
__device__ __forceinline__ float2 unpack2(unsigned long long v) {
    float2 f; asm("mov.b64 {%0, %1}, %2;" : "=f"(f.x), "=f"(f.y) : "l"(v)); return f;
}
__device__ __forceinline__ float ex2f(float x) {
    float r; asm("ex2.approx.f32 %0, %1;" : "=f"(r) : "f"(x)); return r;
}
__device__ __forceinline__ float rcpf(float x) {
    float r; asm("rcp.approx.f32 %0, %1;" : "=f"(r) : "f"(x)); return r;
}
__device__ __forceinline__ float fsig(float x) {
    return rcpf(1.0f + ex2f(-LOG2E * x));
}
__device__ __forceinline__ float ftanhf(float x) {
    return fmaf(rcpf(1.0f + ex2f(-2.0f * LOG2E * x)), 2.0f, -1.0f);
}

// ---------------------------------------------------------------------------
// pre[b][t][g] = b_ih[g] + b_hh[g] + sum_k x[b][t][k] * w_ih[g][k]
// Time-parallel: grid = (128 b-blocks, TCH t-chunks). R4 tiling: thread
// (j=tid>>2, rg=tid&3) computes gates q=0..3 of unit j for rows 2rg, 2rg+1.
// Output layout g_pre[cta][t][g][r] (r innermost, 8 wide) -> STG.64 coalesced.
// ---------------------------------------------------------------------------
__global__ void __launch_bounds__(NTHR, 1)
gemm_pre(const float* __restrict__ x_in,
         const float* __restrict__ w_ih,
         const float* __restrict__ b_ih, const float* __restrict__ b_hh,
         int x_is_scratch)
{
    extern __shared__ float sm[];
    float* wq = sm;                  // [16 kk][256 g][4 kp] = 16384 floats (64 KB)
    float* xb = sm + 16384;          // [8 rows][IPITCH]

    const float* xp = x_is_scratch ? g_h1 : x_in;

    const int tid = threadIdx.x;
    const int j   = tid >> 2;
    const int rg  = tid & 3;
    const int r0  = rg * 2;
    const int row_base = blockIdx.x * ROWS;
    const int t0 = blockIdx.y * TPC;

    // stage w_ih gate-major: wq[kk*1024 + g*4 + kp], k = kk*4 + kp
    for (int idx = tid; idx < 64 * 256; idx += NTHR) {
        int kp = idx & 3;
        int g  = (idx >> 2) & 255;
        int kk = idx >> 10;
        wq[idx] = w_ih[g * 64 + kk * 4 + kp];
    }

    float bias[4];
    #pragma unroll
    for (int q = 0; q < 4; q++) bias[q] = b_ih[q * 64 + j] + b_hh[q * 64 + j];

    float* outp = g_pre + (size_t)blockIdx.x * TT * 2048;

    for (int t = t0; t < t0 + TPC; t++) {
        __syncthreads();   // previous compute finished reading xb
        // load x tile (8 x 64), coalesced
        #pragma unroll
        for (int e = 0; e < 2; e++) {
            int ii = tid + e * 256;
            int r = ii >> 6, u = ii & 63;
            xb[r * IPITCH + u] = xp[((size_t)(row_base + r) * TT + t) * HH + u];
        }
        __syncthreads();

        unsigned long long acc[2][4];
        #pragma unroll
        for (int r = 0; r < 2; r++)
            #pragma unroll
            for (int q = 0; q < 4; q++) acc[r][q] = 0ull;

        const float* v0p = xb + r0 * IPITCH;
        const float* v1p = xb + (r0 + 1) * IPITCH;
        const float* wp  = wq + j * 4;

        #pragma unroll
        for (int kk = 0; kk < 16; kk++) {
            ulonglong2 v0 = *reinterpret_cast<const ulonglong2*>(v0p + kk * 4);
            ulonglong2 v1 = *reinterpret_cast<const ulonglong2*>(v1p + kk * 4);
            const float* wc = wp + kk * 1024;
            #pragma unroll
            for (int q = 0; q < 4; q++) {
                ulonglong2 w2 = *reinterpret_cast<const ulonglong2*>(wc + q * 256);
                fma2(acc[0][q], v0.x, w2.x);
                fma2(acc[0][q], v0.y, w2.y);
                fma2(acc[1][q], v1.x, w2.x);
                fma2(acc[1][q], v1.y, w2.y);
            }
        }

        float* ob = outp + (size_t)t * 2048;
        #pragma unroll
        for (int q = 0; q < 4; q++) {
            float2 f0 = unpack2(acc[0][q]);
            float2 f1 = unpack2(acc[1][q]);
            float2 st = make_float2(f0.x + f0.y + bias[q], f1.x + f1.y + bias[q]);
            *reinterpret_cast<float2*>(ob + (q * 64 + j) * 8 + r0) = st;
        }
    }
}

// ---------------------------------------------------------------------------
// Recurrent-only LSTM: gates = pre(t) + h @ w_hh^T  (K = 64).
// Same R4 tiling; gate-major w_hh tile in smem (conflict-free, 1 wf/load);
// pre(t+1) prefetched from gmem (coalesced LDG.64) during step t's k-loop.
// ---------------------------------------------------------------------------
__global__ void __launch_bounds__(NTHR, 1)
lstm_rec(const float* __restrict__ w_hh, int store_seq, int store_last)
{
    extern __shared__ float sm[];
    float* wq = sm;                  // [16][256][4] = 16384 floats (64 KB)
    float* ib = sm + 16384;          // [2 buf][8 rows][IPITCH] (h only)

    const int tid = threadIdx.x;
    const int j   = tid >> 2;
    const int rg  = tid & 3;
    const int r0  = rg * 2;
    const int row_base = blockIdx.x * ROWS;

    // stage w_hh gate-major
    for (int idx = tid; idx < 64 * 256; idx += NTHR) {
        int kp = idx & 3;
        int g  = (idx >> 2) & 255;
        int kk = idx >> 10;
        wq[idx] = w_hh[g * 64 + kk * 4 + kp];
    }
    // init h buffer 0 = 0
    #pragma unroll
    for (int e = 0; e < 2; e++) {
        int ii = tid + e * 256;
        int r = ii >> 6, u = ii & 63;
        ib[r * IPITCH + u] = 0.0f;
    }

    const float* prep = g_pre + (size_t)blockIdx.x * TT * 2048;

    // preload pre(0): pcur[q] = {row r0, row r0+1} of gate column q*64+j
    float2 pcur[4];
    #pragma unroll
    for (int q = 0; q < 4; q++)
        pcur[q] = *reinterpret_cast<const float2*>(prep + (q * 64 + j) * 8 + r0);

    float c0 = 0.0f, c1 = 0.0f;
    __syncthreads();

    int pb = 0;
    for (int t = 0; t < TT; t++) {
        // prefetch pre(t+1)
        int tn = (t + 1 < TT) ? (t + 1) : t;
        const float* pnb = prep + (size_t)tn * 2048;
        float2 pnext[4];
        #pragma unroll
        for (int q = 0; q < 4; q++)
            pnext[q] = *reinterpret_cast<const float2*>(pnb + (q * 64 + j) * 8 + r0);

        unsigned long long acc[2][4];
        #pragma unroll
        for (int r = 0; r < 2; r++)
            #pragma unroll
            for (int q = 0; q < 4; q++) acc[r][q] = 0ull;

        const float* vb  = ib + pb * (8 * IPITCH);
        const float* v0p = vb + r0 * IPITCH;
        const float* v1p = vb + (r0 + 1) * IPITCH;
        const float* wp  = wq + j * 4;

        #pragma unroll
        for (int kk = 0; kk < 16; kk++) {
            ulonglong2 v0 = *reinterpret_cast<const ulonglong2*>(v0p + kk * 4);
            ulonglong2 v1 = *reinterpret_cast<const ulonglong2*>(v1p + kk * 4);
            const float* wc = wp + kk * 1024;
            #pragma unroll
            for (int q = 0; q < 4; q++) {
                ulonglong2 w2 = *reinterpret_cast<const ulonglong2*>(wc + q * 256);
                fma2(acc[0][q], v0.x, w2.x);
                fma2(acc[0][q], v0.y, w2.y);
                fma2(acc[1][q], v1.x, w2.x);
                fma2(acc[1][q], v1.y, w2.y);
            }
        }

        float z[2][4];
        #pragma unroll
        for (int q = 0; q < 4; q++) {
            float2 f0 = unpack2(acc[0][q]);
            float2 f1 = unpack2(acc[1][q]);
            z[0][q] = f0.x + f0.y + pcur[q].x;
            z[1][q] = f1.x + f1.y + pcur[q].y;
        }

        float i0 = fsig(z[0][0]), f0 = fsig(z[0][1]), g0 = ftanhf(z[0][2]), o0 = fsig(z[0][3]);
        float i1 = fsig(z[1][0]), f1 = fsig(z[1][1]), g1 = ftanhf(z[1][2]), o1 = fsig(z[1][3]);

        c0 = f0 * c0 + i0 * g0;
        c1 = f1 * c1 + i1 * g1;
        float h0 = o0 * ftanhf(c0);
        float h1 = o1 * ftanhf(c1);

        float* nb = ib + (pb ^ 1) * (8 * IPITCH);
        nb[r0 * IPITCH + j]       = h0;
        nb[(r0 + 1) * IPITCH + j] = h1;

        if (store_seq) {
            g_h1[((size_t)(row_base + r0) * TT + t) * HH + j]     = h0;
            g_h1[((size_t)(row_base + r0 + 1) * TT + t) * HH + j] = h1;
        }
        if (store_last && t == TT - 1) {
            g_hlast[(row_base + r0) * HH + j]     = h0;
            g_hlast[(row_base + r0 + 1) * HH + j] = h1;
        }

        __syncthreads();
        pb ^= 1;
        #pragma unroll
        for (int q = 0; q < 4; q++) pcur[q] = pnext[q];
    }
}

// out[b][o] = softplus(h_last[b] . fc_w[o] + fc_b[o]),  O=32
__global__ void fc_softplus(const float* __restrict__ fc_w,
                            const float* __restrict__ fc_b,
                            float* __restrict__ out)
{
    __shared__ float wsh[64 * 32];
    __shared__ float bsh[32];
    const int tid = threadIdx.x;     // 128 threads

    for (int idx = tid; idx < 64 * 32; idx += 128) {
        int k = idx >> 5, o = idx & 31;
        wsh[idx] = fc_w[o * 64 + k];
    }
    if (tid < 32) bsh[tid] = fc_b[tid];
    __syncthreads();

    int gid = blockIdx.x * 128 + tid;
    int b = gid >> 5, o = gid & 31;
    const float* hr = g_hlast + b * 64;

    float z = bsh[o];
    #pragma unroll
    for (int k = 0; k < 64; k++)
        z += hr[k] * wsh[k * 32 + o];

    float r = (z > 20.0f) ? z : log1pf(__expf(z));
    out[gid] = r;
}

extern "C" void kernel_launch(void* const* d_in, const int* in_sizes, int n_in,
                              void* d_out, int out_size)
{
    (void)in_sizes; (void)n_in; (void)out_size;
    const float* x    = (const float*)d_in[0];
    const float* wih0 = (const float*)d_in[1];
    const float* whh0 = (const float*)d_in[2];
    const float* bih0 = (const float*)d_in[3];
    const float* bhh0 = (const float*)d_in[4];
    const float* wih1 = (const float*)d_in[5];
    const float* whh1 = (const float*)d_in[6];
    const float* bih1 = (const float*)d_in[7];
    const float* bhh1 = (const float*)d_in[8];
    const float* fcw  = (const float*)d_in[9];
    const float* fcb  = (const float*)d_in[10];
    float* out = (float*)d_out;

    const size_t smemA = (size_t)(16384 + ROWS * IPITCH) * sizeof(float);      // ~67.7 KB
    const size_t smemB = (size_t)(16384 + 2 * ROWS * IPITCH) * sizeof(float);  // ~69.9 KB
    cudaFuncSetAttribute(gemm_pre, cudaFuncAttributeMaxDynamicSharedMemorySize, (int)smemA);
    cudaFuncSetAttribute(lstm_rec, cudaFuncAttributeMaxDynamicSharedMemorySize, (int)smemB);

    dim3 pre_grid(BB / ROWS, TCH);

    // layer 0
    gemm_pre<<<pre_grid, NTHR, smemA>>>(x, wih0, bih0, bhh0, 0);
    lstm_rec<<<BB / ROWS, NTHR, smemB>>>(whh0, 1, 0);
    // layer 1 (input = g_h1)
    gemm_pre<<<pre_grid, NTHR, smemA>>>(nullptr, wih1, bih1, bhh1, 1);
    lstm_rec<<<BB / ROWS, NTHR, smemB>>>(whh1, 0, 1);
    // FC + softplus
    fc_softplus<<<(BB * 32) / 128, 128>>>(fcw, fcb, out);
}